// round 3
// baseline (speedup 1.0000x reference)
#include <cuda_runtime.h>
#include <cuda_bf16.h>
#include <cstdint>

// Problem constants (fixed by the reference generator)
#define F_DIM 16
#define B_GRAPHS 8
#define NVALS 9               // base + 8 segment dots
#define ACC_BLOCKS 2048
#define ACC_THREADS 256

// Scratch for per-block partials, transposed: g_partials[k][block].
// Written fully every replay -> no zeroing needed.
__device__ float g_partials[NVALS][ACC_BLOCKS];
// Ticket counter: starts at 0 (module load), reset to 0 by the last block
// every launch -> deterministic across graph replays.
__device__ unsigned int g_ticket;

__global__ __launch_bounds__(ACC_THREADS) void fused_kernel(
    const float* __restrict__ inp,
    const float* __restrict__ tgt,
    const int* __restrict__ batch,
    float* __restrict__ out,
    int n)
{
    float base = 0.0f;
    float dots[B_GRAPHS];
#pragma unroll
    for (int b = 0; b < B_GRAPHS; b++) dots[b] = 0.0f;

    const int stride = gridDim.x * blockDim.x;
    for (int i = blockIdx.x * blockDim.x + threadIdx.x; i < n; i += stride) {
        const float4* a = reinterpret_cast<const float4*>(inp + (size_t)i * F_DIM);
        const float4* t = reinterpret_cast<const float4*>(tgt + (size_t)i * F_DIM);
        float dot = 0.0f, sq = 0.0f;
#pragma unroll
        for (int j = 0; j < 4; j++) {
            float4 x = a[j];
            float4 y = t[j];
            sq  = fmaf(x.x, x.x, sq);  sq = fmaf(x.y, x.y, sq);
            sq  = fmaf(x.z, x.z, sq);  sq = fmaf(x.w, x.w, sq);
            sq  = fmaf(y.x, y.x, sq);  sq = fmaf(y.y, y.y, sq);
            sq  = fmaf(y.z, y.z, sq);  sq = fmaf(y.w, y.w, sq);
            dot = fmaf(x.x, y.x, dot); dot = fmaf(x.y, y.y, dot);
            dot = fmaf(x.z, y.z, dot); dot = fmaf(x.w, y.w, dot);
        }
        base += sq;
        int bid = batch[i] & (B_GRAPHS - 1);
        // predicated adds (unrolled) — avoids local-memory spill from dynamic indexing
#pragma unroll
        for (int b = 0; b < B_GRAPHS; b++) {
            if (bid == b) dots[b] += dot;
        }
    }

    // pack the 9 values and reduce within the block
    float vals[NVALS];
    vals[0] = base;
#pragma unroll
    for (int b = 0; b < B_GRAPHS; b++) vals[b + 1] = dots[b];

#pragma unroll
    for (int k = 0; k < NVALS; k++) {
#pragma unroll
        for (int off = 16; off > 0; off >>= 1)
            vals[k] += __shfl_down_sync(0xFFFFFFFFu, vals[k], off);
    }

    __shared__ float smem[ACC_THREADS / 32][NVALS];
    __shared__ int s_is_last;
    int warp = threadIdx.x >> 5;
    int lane = threadIdx.x & 31;
    if (lane == 0) {
#pragma unroll
        for (int k = 0; k < NVALS; k++) smem[warp][k] = vals[k];
    }
    __syncthreads();

    if (threadIdx.x == 0) {
        float o[NVALS];
#pragma unroll
        for (int k = 0; k < NVALS; k++) o[k] = smem[0][k];
#pragma unroll
        for (int w = 1; w < ACC_THREADS / 32; w++) {
#pragma unroll
            for (int k = 0; k < NVALS; k++) o[k] += smem[w][k];
        }
#pragma unroll
        for (int k = 0; k < NVALS; k++)
            g_partials[k][blockIdx.x] = o[k];

        __threadfence();
        unsigned int ticket = atomicAdd(&g_ticket, 1u);
        s_is_last = (ticket == (unsigned)(gridDim.x - 1)) ? 1 : 0;
    }
    __syncthreads();

    if (!s_is_last) return;

    // ----- Last block: reduce all partials (coalesced, transposed layout) -----
    float fv[NVALS];
#pragma unroll
    for (int k = 0; k < NVALS; k++) fv[k] = 0.0f;

    for (int r = threadIdx.x; r < ACC_BLOCKS; r += ACC_THREADS) {
#pragma unroll
        for (int k = 0; k < NVALS; k++)
            fv[k] += g_partials[k][r];
    }

#pragma unroll
    for (int k = 0; k < NVALS; k++) {
#pragma unroll
        for (int off = 16; off > 0; off >>= 1)
            fv[k] += __shfl_down_sync(0xFFFFFFFFu, fv[k], off);
    }

    __syncthreads();   // reuse smem safely
    if (lane == 0) {
#pragma unroll
        for (int k = 0; k < NVALS; k++) smem[warp][k] = fv[k];
    }
    __syncthreads();

    if (threadIdx.x == 0) {
        float acc[NVALS];
#pragma unroll
        for (int k = 0; k < NVALS; k++) acc[k] = smem[0][k];
#pragma unroll
        for (int w = 1; w < ACC_THREADS / 32; w++) {
#pragma unroll
            for (int k = 0; k < NVALS; k++) acc[k] += smem[w][k];
        }
        // min over all 2^B sign combos == base - 2 * sum_b |dot_b|
        float s = 0.0f;
#pragma unroll
        for (int b = 0; b < B_GRAPHS; b++) s += fabsf(acc[b + 1]);
        out[0] = acc[0] - 2.0f * s;
        g_ticket = 0u;   // reset for next (graph-replayed) launch
    }
}

extern "C" void kernel_launch(void* const* d_in, const int* in_sizes, int n_in,
                              void* d_out, int out_size)
{
    const float* inp   = (const float*)d_in[0];
    const float* tgt   = (const float*)d_in[1];
    const int*   batch = (const int*)d_in[2];
    float* out = (float*)d_out;

    int n = in_sizes[2];  // number of nodes (batch vector length)

    fused_kernel<<<ACC_BLOCKS, ACC_THREADS>>>(inp, tgt, batch, out, n);
}